// round 14
// baseline (speedup 1.0000x reference)
#include <cuda_runtime.h>
#include <cuda_fp16.h>
#include <cstdint>

// ---------------------------------------------------------------------------
// PHMLinear via Kronecker factorization, warp-level HMMA (baseline PTX).
//   Per token (X = x row viewed 64x64):  Y = sum_b A_b @ X @ B_b^T + bias
//   U_b = A_b @ X (f32 accum + cvt),  Y += U_b @ B_b^T (f32 accum).
//
// TWO CTAs PER SM, split by output-row half (proven R13, 359us). This round:
// ILP restructure -- b outer / mc inner, A-fragments hoisted per b (halves
// A-ldsm), XB cached for both mc (64 regs), and G1/cvt/G2 phases laid out so
// G2(mc0) overlaps G1(mc1) in the scheduler window.
// 128 threads/CTA: 4 warps = 2 tokens x 2 sixteen-row quarters.
// ---------------------------------------------------------------------------

#define NTOK  16384
#define TILES 8192        // 2 tokens per tile

#define OFF_A    0        // 256 rows x 128B, fp16 A[(b, i_half), j], swizzled
#define OFF_B    32768    // 512 rows x 128B, fp16 B[(b,k), m], swizzled
#define OFF_X    98304    // 2 tokens x 64 rows x 128B, fp16, swizzled
#define SMEM_BYTES 114688

__device__ __forceinline__ uint32_t swz(uint32_t o) { return o ^ ((o >> 3) & 0x70); }

__device__ __forceinline__ uint32_t s2u(const void* p) {
    uint32_t a;
    asm("{ .reg .u64 t; cvta.to.shared.u64 t, %1; cvt.u32.u64 %0, t; }" : "=r"(a) : "l"(p));
    return a;
}
__device__ __forceinline__ uint32_t h2u(__half2 h) { return *reinterpret_cast<uint32_t*>(&h); }

__device__ __forceinline__ void ldsm4(uint32_t a, uint32_t* r) {
    asm volatile("ldmatrix.sync.aligned.m8n8.x4.shared.b16 {%0,%1,%2,%3}, [%4];"
                 : "=r"(r[0]), "=r"(r[1]), "=r"(r[2]), "=r"(r[3]) : "r"(a));
}
__device__ __forceinline__ void ldsm4t(uint32_t a, uint32_t* r) {
    asm volatile("ldmatrix.sync.aligned.m8n8.x4.trans.shared.b16 {%0,%1,%2,%3}, [%4];"
                 : "=r"(r[0]), "=r"(r[1]), "=r"(r[2]), "=r"(r[3]) : "r"(a));
}
__device__ __forceinline__ void mma_f32(float* d, const uint32_t* a, const uint32_t* b) {
    asm volatile(
        "mma.sync.aligned.m16n8k16.row.col.f32.f16.f16.f32 "
        "{%0,%1,%2,%3}, {%4,%5,%6,%7}, {%8,%9}, {%0,%1,%2,%3};"
        : "+f"(d[0]), "+f"(d[1]), "+f"(d[2]), "+f"(d[3])
        : "r"(a[0]), "r"(a[1]), "r"(a[2]), "r"(a[3]), "r"(b[0]), "r"(b[1]));
}

extern __shared__ char smem[];

__global__ void __launch_bounds__(128, 2)
phm_kernel(const float* __restrict__ x, const float* __restrict__ A,
           const float* __restrict__ B, const float* __restrict__ bias,
           float* __restrict__ out)
{
    const int tid   = threadIdx.x;
    const int wid   = tid >> 5;
    const int lane  = tid & 31;
    const int ihalf = blockIdx.x & 1;          // which 32 i-rows
    const int pair  = blockIdx.x >> 1;
    const int npair = (int)gridDim.x >> 1;
    const uint32_t sbase = s2u(smem);

    // ---- one-time: A-half + full B, fp32 -> fp16 swizzled smem ----
    {
        const float4* Ag = (const float4*)A;
        const float4* Bg = (const float4*)B;
        for (int v = tid; v < 4096; v += 128) {
            int lrow = v >> 4, m4 = v & 15;
            int b = lrow >> 5, lr = lrow & 31;
            float4 f = Ag[(b * 64 + ihalf * 32 + lr) * 16 + m4];
            uint32_t off = swz((uint32_t)(lrow * 128 + m4 * 8));
            *(uint2*)(smem + OFF_A + off) =
                make_uint2(h2u(__floats2half2_rn(f.x, f.y)), h2u(__floats2half2_rn(f.z, f.w)));
        }
        for (int v = tid; v < 8192; v += 128) {
            int row = v >> 4, m4 = v & 15;
            float4 f = Bg[v];
            uint32_t off = swz((uint32_t)(row * 128 + m4 * 8));
            *(uint2*)(smem + OFF_B + off) =
                make_uint2(h2u(__floats2half2_rn(f.x, f.y)), h2u(__floats2half2_rn(f.z, f.w)));
        }
    }

    const int tl    = wid >> 1;        // token slot 0..1 within tile
    const int wq    = wid & 1;         // 16-row quarter within CTA's half
    const int l16   = lane & 15;       // ldmatrix row component
    const int lhi   = lane >> 4;       // ldmatrix col-half component
    const int b2row = ((lane >> 4) << 3) + (lane & 7);   // B2 pattern row part
    const int b2c   = (lane >> 3) & 1;                   // B2 pattern col part
    const int gi    = lane >> 2;       // mma group row
    const int gk    = (lane & 3) << 1; // mma group col pair

    const uint32_t Xt = sbase + OFF_X + tl * 8192;
    const float2* bg  = (const float2*)bias;
    const int i0      = ihalf * 32 + wq * 16 + gi;       // output row base

    for (int tile = pair; tile < TILES; tile += npair) {
        __syncthreads();   // previous compute done reading X
        // ---- stage X: 2 tokens fp32 -> fp16 swizzled (CTA-wide) ----
        {
            const float4* xg = (const float4*)(x + (size_t)tile * 8192);
            #pragma unroll
            for (int p = 0; p < 16; p++) {
                int v = tid + (p << 7);          // 0..2047 float4s
                float4 f = xg[v];
                int w = v & 1023, row = w >> 4, m4 = w & 15;
                uint32_t off = (uint32_t)((v >> 10) * 8192) + swz((uint32_t)(row * 128 + m4 * 8));
                *(uint2*)(smem + OFF_X + off) =
                    make_uint2(h2u(__floats2half2_rn(f.x, f.y)),
                               h2u(__floats2half2_rn(f.z, f.w)));
            }
        }
        __syncthreads();

        // ---- init Y with bias (L1-resident __ldg) ----
        float Y[8][4];
        #pragma unroll
        for (int nt = 0; nt < 8; nt++) {
            int k0 = nt * 8 + gk;
            float2 b01 = __ldg(bg + ((i0 * 64 + k0) >> 1));
            float2 b23 = __ldg(bg + (((i0 + 8) * 64 + k0) >> 1));
            Y[nt][0] = b01.x; Y[nt][1] = b01.y;
            Y[nt][2] = b23.x; Y[nt][3] = b23.y;
        }

        // ---- cache X B-fragments for BOTH 32-wide m-chunks (64 regs) ----
        uint32_t XB[2][4][2][4];
        #pragma unroll
        for (int mc = 0; mc < 2; mc++)
            #pragma unroll
            for (int jt = 0; jt < 4; jt++) {
                int row = jt * 16 + l16;
                #pragma unroll
                for (int ntp = 0; ntp < 2; ntp++) {
                    uint32_t c = (uint32_t)(mc * 4 + ntp * 2 + lhi) ^ (uint32_t)(row & 7);
                    ldsm4t(Xt + (uint32_t)(row * 128) + (c << 4), XB[mc][jt][ntp]);
                }
            }

        #pragma unroll
        for (int b = 0; b < 8; b++) {
            // ---- hoist A fragments for this b (all jt; shared by both mc) ----
            uint32_t AF[4][4];
            #pragma unroll
            for (int jt = 0; jt < 4; jt++) {
                int lrow = b * 32 + wq * 16 + l16;   // local A row
                uint32_t c = (uint32_t)(jt * 2 + lhi) ^ (uint32_t)(lrow & 7);
                ldsm4(sbase + OFF_A + (uint32_t)(lrow * 128) + (c << 4), AF[jt]);
            }

            // ---- GEMM1 both mc, cvt each; G2(mc0) can overlap G1(mc1) ----
            uint32_t UA[2][2][4];
            #pragma unroll
            for (int mc = 0; mc < 2; mc++) {
                float U[4][4];
                #pragma unroll
                for (int nt = 0; nt < 4; nt++)
                    #pragma unroll
                    for (int e = 0; e < 4; e++) U[nt][e] = 0.f;

                #pragma unroll
                for (int jt = 0; jt < 4; jt++)
                    #pragma unroll
                    for (int nt = 0; nt < 4; nt++)
                        mma_f32(U[nt], AF[jt], XB[mc][jt][nt >> 1] + (nt & 1) * 2);

                #pragma unroll
                for (int mt = 0; mt < 2; mt++) {
                    UA[mc][mt][0] = h2u(__floats2half2_rn(U[2*mt][0],   U[2*mt][1]));
                    UA[mc][mt][1] = h2u(__floats2half2_rn(U[2*mt][2],   U[2*mt][3]));
                    UA[mc][mt][2] = h2u(__floats2half2_rn(U[2*mt+1][0], U[2*mt+1][1]));
                    UA[mc][mt][3] = h2u(__floats2half2_rn(U[2*mt+1][2], U[2*mt+1][3]));
                }
            }

            // ---- GEMM2 (f32 accum): Y += U @ B_b^T, both m-chunks ----
            #pragma unroll
            for (int mc = 0; mc < 2; mc++)
                #pragma unroll
                for (int kop = 0; kop < 4; kop++) {
                    uint32_t BF[2][4];
                    #pragma unroll
                    for (int mt = 0; mt < 2; mt++) {
                        int row = b * 64 + kop * 16 + b2row;
                        uint32_t c = (uint32_t)(mc * 4 + mt * 2 + b2c) ^ (uint32_t)(lane & 7);
                        ldsm4(sbase + OFF_B + (uint32_t)(row * 128) + (c << 4), BF[mt]);
                    }
                    #pragma unroll
                    for (int mt = 0; mt < 2; mt++)
                        #pragma unroll
                        for (int h = 0; h < 2; h++)
                            mma_f32(Y[kop * 2 + h], UA[mc][mt], BF[mt] + h * 2);
                }
        }

        // ---- store Y (bias already included) ----
        {
            const int token = tile * 2 + tl;
            float* orow = out + (size_t)token * 4096;
            #pragma unroll
            for (int nt = 0; nt < 8; nt++) {
                int k0 = nt * 8 + gk;
                *(float2*)(orow + (size_t)i0 * 64 + k0)       = make_float2(Y[nt][0], Y[nt][1]);
                *(float2*)(orow + (size_t)(i0 + 8) * 64 + k0) = make_float2(Y[nt][2], Y[nt][3]);
            }
        }
    }
}

extern "C" void kernel_launch(void* const* d_in, const int* in_sizes, int n_in,
                              void* d_out, int out_size) {
    const float* x    = (const float*)d_in[0];
    const float* A    = (const float*)d_in[1];
    const float* B    = (const float*)d_in[2];
    const float* bias = (const float*)d_in[3];
    float* out        = (float*)d_out;

    cudaFuncSetAttribute(phm_kernel, cudaFuncAttributeMaxDynamicSharedMemorySize, SMEM_BYTES);
    int nsm = 148;
    cudaDeviceGetAttribute(&nsm, cudaDevAttrMultiProcessorCount, 0);
    if (nsm <= 0 || nsm > 1024) nsm = 148;

    phm_kernel<<<2 * nsm, 128, SMEM_BYTES>>>(x, A, B, bias, out);
}

// round 15
// speedup vs baseline: 1.0615x; 1.0615x over previous
#include <cuda_runtime.h>
#include <cuda_fp16.h>
#include <cstdint>

// ---------------------------------------------------------------------------
// PHMLinear via Kronecker factorization, warp-level HMMA (baseline PTX).
//   Per token (X = x row viewed 64x64):  Y = sum_b A_b @ X @ B_b^T + bias
//   U_b = A_b @ X (f32 accum + cvt),  Y += U_b @ B_b^T (f32 accum).
//
// TWO CTAs PER SM, split by output-row half (R13, 359us) + micro-scheduling:
//   - G1 loads all 4 A-fragments before its mma run
//   - G2 software-pipelines BF (kop+1 prefetch)
//   - X staging uses STS.128 (paired LDG.128)
// 128 threads/CTA: 4 warps = 2 tokens x 2 sixteen-row quarters.
// ---------------------------------------------------------------------------

#define NTOK  16384
#define TILES 8192        // 2 tokens per tile

#define OFF_A    0        // 256 rows x 128B, fp16 A[(b, i_half), j], swizzled
#define OFF_B    32768    // 512 rows x 128B, fp16 B[(b,k), m], swizzled
#define OFF_X    98304    // 2 tokens x 64 rows x 128B, fp16, swizzled
#define SMEM_BYTES 114688

__device__ __forceinline__ uint32_t swz(uint32_t o) { return o ^ ((o >> 3) & 0x70); }

__device__ __forceinline__ uint32_t s2u(const void* p) {
    uint32_t a;
    asm("{ .reg .u64 t; cvta.to.shared.u64 t, %1; cvt.u32.u64 %0, t; }" : "=r"(a) : "l"(p));
    return a;
}
__device__ __forceinline__ uint32_t h2u(__half2 h) { return *reinterpret_cast<uint32_t*>(&h); }

__device__ __forceinline__ void ldsm4(uint32_t a, uint32_t* r) {
    asm volatile("ldmatrix.sync.aligned.m8n8.x4.shared.b16 {%0,%1,%2,%3}, [%4];"
                 : "=r"(r[0]), "=r"(r[1]), "=r"(r[2]), "=r"(r[3]) : "r"(a));
}
__device__ __forceinline__ void ldsm4t(uint32_t a, uint32_t* r) {
    asm volatile("ldmatrix.sync.aligned.m8n8.x4.trans.shared.b16 {%0,%1,%2,%3}, [%4];"
                 : "=r"(r[0]), "=r"(r[1]), "=r"(r[2]), "=r"(r[3]) : "r"(a));
}
__device__ __forceinline__ void mma_f32(float* d, const uint32_t* a, const uint32_t* b) {
    asm volatile(
        "mma.sync.aligned.m16n8k16.row.col.f32.f16.f16.f32 "
        "{%0,%1,%2,%3}, {%4,%5,%6,%7}, {%8,%9}, {%0,%1,%2,%3};"
        : "+f"(d[0]), "+f"(d[1]), "+f"(d[2]), "+f"(d[3])
        : "r"(a[0]), "r"(a[1]), "r"(a[2]), "r"(a[3]), "r"(b[0]), "r"(b[1]));
}

extern __shared__ char smem[];

__global__ void __launch_bounds__(128, 2)
phm_kernel(const float* __restrict__ x, const float* __restrict__ A,
           const float* __restrict__ B, const float* __restrict__ bias,
           float* __restrict__ out)
{
    const int tid   = threadIdx.x;
    const int wid   = tid >> 5;
    const int lane  = tid & 31;
    const int ihalf = blockIdx.x & 1;          // which 32 i-rows
    const int pair  = blockIdx.x >> 1;
    const int npair = (int)gridDim.x >> 1;
    const uint32_t sbase = s2u(smem);

    // ---- one-time: A-half + full B, fp32 -> fp16 swizzled smem ----
    {
        const float4* Ag = (const float4*)A;
        const float4* Bg = (const float4*)B;
        for (int v = tid; v < 4096; v += 128) {
            int lrow = v >> 4, m4 = v & 15;
            int b = lrow >> 5, lr = lrow & 31;
            float4 f = Ag[(b * 64 + ihalf * 32 + lr) * 16 + m4];
            uint32_t off = swz((uint32_t)(lrow * 128 + m4 * 8));
            *(uint2*)(smem + OFF_A + off) =
                make_uint2(h2u(__floats2half2_rn(f.x, f.y)), h2u(__floats2half2_rn(f.z, f.w)));
        }
        for (int v = tid; v < 8192; v += 128) {
            int row = v >> 4, m4 = v & 15;
            float4 f = Bg[v];
            uint32_t off = swz((uint32_t)(row * 128 + m4 * 8));
            *(uint2*)(smem + OFF_B + off) =
                make_uint2(h2u(__floats2half2_rn(f.x, f.y)), h2u(__floats2half2_rn(f.z, f.w)));
        }
    }

    const int tl    = wid >> 1;        // token slot 0..1 within tile
    const int wq    = wid & 1;         // 16-row quarter within CTA's half
    const int l16   = lane & 15;       // ldmatrix row component
    const int lhi   = lane >> 4;       // ldmatrix col-half component
    const int b2row = ((lane >> 4) << 3) + (lane & 7);   // B2 pattern row part
    const int b2c   = (lane >> 3) & 1;                   // B2 pattern col part
    const int gi    = lane >> 2;       // mma group row
    const int gk    = (lane & 3) << 1; // mma group col pair

    const uint32_t Xt = sbase + OFF_X + tl * 8192;
    const float2* bg  = (const float2*)bias;
    const int i0      = ihalf * 32 + wq * 16 + gi;       // output row base

    for (int tile = pair; tile < TILES; tile += npair) {
        __syncthreads();   // previous compute done reading X
        // ---- stage X: 2 tokens fp32 -> fp16 swizzled, STS.128 ----
        {
            const float4* xg = (const float4*)(x + (size_t)tile * 8192);
            #pragma unroll
            for (int p = 0; p < 8; p++) {
                int v2 = tid + (p << 7);         // 0..1023 float4-pairs
                float4 f0 = xg[v2 * 2];
                float4 f1 = xg[v2 * 2 + 1];
                int w = (v2 * 2) & 1023, row = w >> 4, m4 = w & 15;
                uint32_t off = (uint32_t)(((v2 * 2) >> 10) * 8192)
                             + swz((uint32_t)(row * 128 + m4 * 8));
                uint4 pk;
                pk.x = h2u(__floats2half2_rn(f0.x, f0.y));
                pk.y = h2u(__floats2half2_rn(f0.z, f0.w));
                pk.z = h2u(__floats2half2_rn(f1.x, f1.y));
                pk.w = h2u(__floats2half2_rn(f1.z, f1.w));
                *(uint4*)(smem + OFF_X + off) = pk;
            }
        }
        __syncthreads();

        // ---- init Y with bias (L1-resident __ldg) ----
        float Y[8][4];
        #pragma unroll
        for (int nt = 0; nt < 8; nt++) {
            int k0 = nt * 8 + gk;
            float2 b01 = __ldg(bg + ((i0 * 64 + k0) >> 1));
            float2 b23 = __ldg(bg + (((i0 + 8) * 64 + k0) >> 1));
            Y[nt][0] = b01.x; Y[nt][1] = b01.y;
            Y[nt][2] = b23.x; Y[nt][3] = b23.y;
        }

        #pragma unroll
        for (int mc = 0; mc < 2; mc++) {
            // X B-fragments for this 32-wide m-chunk (shared across all b)
            uint32_t XB[4][2][4];
            #pragma unroll
            for (int jt = 0; jt < 4; jt++) {
                int row = jt * 16 + l16;
                #pragma unroll
                for (int ntp = 0; ntp < 2; ntp++) {
                    uint32_t c = (uint32_t)(mc * 4 + ntp * 2 + lhi) ^ (uint32_t)(row & 7);
                    ldsm4t(Xt + (uint32_t)(row * 128) + (c << 4), XB[jt][ntp]);
                }
            }
            #pragma unroll
            for (int b = 0; b < 8; b++) {
                // ---- GEMM1: batch all 4 AF ldsm, then 16 mma ----
                uint32_t AF[4][4];
                {
                    int lrow = b * 32 + wq * 16 + l16;   // local A row
                    #pragma unroll
                    for (int jt = 0; jt < 4; jt++) {
                        uint32_t c = (uint32_t)(jt * 2 + lhi) ^ (uint32_t)(lrow & 7);
                        ldsm4(sbase + OFF_A + (uint32_t)(lrow * 128) + (c << 4), AF[jt]);
                    }
                }
                float U[4][4];
                #pragma unroll
                for (int nt = 0; nt < 4; nt++)
                    #pragma unroll
                    for (int e = 0; e < 4; e++) U[nt][e] = 0.f;
                #pragma unroll
                for (int jt = 0; jt < 4; jt++)
                    #pragma unroll
                    for (int nt = 0; nt < 4; nt++)
                        mma_f32(U[nt], AF[jt], XB[jt][nt >> 1] + (nt & 1) * 2);

                // ---- cvt U (f32) -> GEMM2 A-fragments (f16x2) ----
                uint32_t UA[2][4];
                #pragma unroll
                for (int mt = 0; mt < 2; mt++) {
                    UA[mt][0] = h2u(__floats2half2_rn(U[2*mt][0],   U[2*mt][1]));
                    UA[mt][1] = h2u(__floats2half2_rn(U[2*mt][2],   U[2*mt][3]));
                    UA[mt][2] = h2u(__floats2half2_rn(U[2*mt+1][0], U[2*mt+1][1]));
                    UA[mt][3] = h2u(__floats2half2_rn(U[2*mt+1][2], U[2*mt+1][3]));
                }

                // ---- GEMM2 with BF software pipeline (kop+1 prefetch) ----
                {
                    const int brow = b * 64 + b2row;
                    uint32_t BF[2][4];
                    #pragma unroll
                    for (int mt = 0; mt < 2; mt++) {
                        uint32_t c = (uint32_t)(mc * 4 + mt * 2 + b2c) ^ (uint32_t)(lane & 7);
                        ldsm4(sbase + OFF_B + (uint32_t)(brow * 128) + (c << 4), BF[mt]);
                    }
                    #pragma unroll
                    for (int kop = 0; kop < 4; kop++) {
                        uint32_t BN[2][4];
                        if (kop < 3) {
                            int row = brow + (kop + 1) * 16;
                            #pragma unroll
                            for (int mt = 0; mt < 2; mt++) {
                                uint32_t c = (uint32_t)(mc * 4 + mt * 2 + b2c) ^ (uint32_t)(lane & 7);
                                ldsm4(sbase + OFF_B + (uint32_t)(row * 128) + (c << 4), BN[mt]);
                            }
                        }
                        #pragma unroll
                        for (int mt = 0; mt < 2; mt++)
                            #pragma unroll
                            for (int h = 0; h < 2; h++)
                                mma_f32(Y[kop * 2 + h], UA[mt], BF[mt] + h * 2);
                        #pragma unroll
                        for (int mt = 0; mt < 2; mt++)
                            #pragma unroll
                            for (int e = 0; e < 4; e++)
                                BF[mt][e] = BN[mt][e];
                    }
                }
            }
        }

        // ---- store Y (bias already included) ----
        {
            const int token = tile * 2 + tl;
            float* orow = out + (size_t)token * 4096;
            #pragma unroll
            for (int nt = 0; nt < 8; nt++) {
                int k0 = nt * 8 + gk;
                *(float2*)(orow + (size_t)i0 * 64 + k0)       = make_float2(Y[nt][0], Y[nt][1]);
                *(float2*)(orow + (size_t)(i0 + 8) * 64 + k0) = make_float2(Y[nt][2], Y[nt][3]);
            }
        }
    }
}

extern "C" void kernel_launch(void* const* d_in, const int* in_sizes, int n_in,
                              void* d_out, int out_size) {
    const float* x    = (const float*)d_in[0];
    const float* A    = (const float*)d_in[1];
    const float* B    = (const float*)d_in[2];
    const float* bias = (const float*)d_in[3];
    float* out        = (float*)d_out;

    cudaFuncSetAttribute(phm_kernel, cudaFuncAttributeMaxDynamicSharedMemorySize, SMEM_BYTES);
    int nsm = 148;
    cudaDeviceGetAttribute(&nsm, cudaDevAttrMultiProcessorCount, 0);
    if (nsm <= 0 || nsm > 1024) nsm = 148;

    phm_kernel<<<2 * nsm, 128, SMEM_BYTES>>>(x, A, B, bias, out);
}